// round 9
// baseline (speedup 1.0000x reference)
#include <cuda_runtime.h>
#include <cstdint>

// Problem: B=8, S=128, V=32000, E=768
// input:  one-hot [B,S,V] f32  (exactly one 1.0 per row, rest 0.0)
// weight: [V,E] f32
// out:    [B,S,E] f32 = weight[argnonzero(input[b,s,:]), :]
//
// Warp-autonomous: each warp independently scans a 125-float4 (2 KB) segment,
// reduces via shfl only (no shared memory, no __syncthreads), so no warp ever
// idles on a block barrier while the SM's load pipe drains.
// Index recovery: acc = sum(v[i] * (i+1)); found <=> acc != 0 (handles idx=0);
// idx = round(acc) - 1. Exact in fp32 since all values <= 32000 < 2^24.

#define NROWS    1024
#define VEC_V    8000         // float4 per row
#define WSEG     125          // float4 per warp segment (2 KB)
#define WPB      8            // warps per block
#define THREADS  (WPB * 32)
#define VEC_E    192          // float4 per output row

__global__ __launch_bounds__(THREADS, 8)
void onehot_embed_kernel(const float4* __restrict__ oh,
                         const float4* __restrict__ w,
                         float4* __restrict__ out)
{
    const int unit  = blockIdx.x;          // 8192 CTAs
    const int row   = unit >> 3;
    const int wblk  = unit & 7;
    const int warp  = threadIdx.x >> 5;
    const int lane  = threadIdx.x & 31;
    const int wseg  = wblk * WPB + warp;   // 0..63 within row

    const float4* __restrict__ r = oh + (size_t)row * VEC_V + wseg * WSEG;

    // ---- front-batched loads: 3 unconditional + 1 predicated (125 = 3*32 + 29)
    const int i3 = lane + 96;
    float4 v0 = __ldcs(&r[lane]);
    float4 v1 = __ldcs(&r[lane + 32]);
    float4 v2 = __ldcs(&r[lane + 64]);
    float4 v3 = make_float4(0.f, 0.f, 0.f, 0.f);
    if (i3 < WSEG) v3 = __ldcs(&r[i3]);

    // ---- exact dot with (global_index + 1) ----
    const int gbase = wseg * WSEG;         // float4 index base within row
    float b0 = (float)(4 * (gbase + lane)      + 1);
    float b1 = (float)(4 * (gbase + lane + 32) + 1);
    float b2 = (float)(4 * (gbase + lane + 64) + 1);
    float b3 = (float)(4 * (gbase + i3)        + 1);

    float acc;
    acc  = v0.x * b0 + v0.y * (b0 + 1.0f) + v0.z * (b0 + 2.0f) + v0.w * (b0 + 3.0f);
    acc += v1.x * b1 + v1.y * (b1 + 1.0f) + v1.z * (b1 + 2.0f) + v1.w * (b1 + 3.0f);
    acc += v2.x * b2 + v2.y * (b2 + 1.0f) + v2.z * (b2 + 2.0f) + v2.w * (b2 + 3.0f);
    acc += v3.x * b3 + v3.y * (b3 + 1.0f) + v3.z * (b3 + 2.0f) + v3.w * (b3 + 3.0f);

    // ---- warp-only reduce ----
    #pragma unroll
    for (int d = 16; d; d >>= 1)
        acc += __shfl_xor_sync(0xffffffffu, acc, d);

    // ---- the warp holding the 1.0 gathers the weight row ----
    if (acc != 0.0f) {
        const int idx = (int)(acc + 0.5f) - 1;
        const float4* __restrict__ wr = w   + (size_t)idx * VEC_E;
        float4*       __restrict__ o  = out + (size_t)row * VEC_E;
        #pragma unroll
        for (int j = lane; j < VEC_E; j += 32)
            o[j] = __ldg(&wr[j]);
    }
}

extern "C" void kernel_launch(void* const* d_in, const int* in_sizes, int n_in,
                              void* d_out, int out_size)
{
    // metadata order: input (one-hot), weight. Defensive swap by size.
    const float4* oh = (const float4*)d_in[0];
    const float4* w  = (const float4*)d_in[1];
    if (n_in >= 2 && in_sizes[0] < in_sizes[1]) {  // weight (24.6M) < one-hot (32.8M)
        oh = (const float4*)d_in[1];
        w  = (const float4*)d_in[0];
    }
    onehot_embed_kernel<<<NROWS * 8, THREADS>>>(oh, w, (float4*)d_out);
}

// round 12
// speedup vs baseline: 1.0637x; 1.0637x over previous
#include <cuda_runtime.h>
#include <cstdint>

// Problem: B=8, S=128, V=32000, E=768
// input:  one-hot [B,S,V] f32  (exactly one 1.0 per row, rest 0.0)
// weight: [V,E] f32
// out:    [B,S,E] f32 = weight[argnonzero(input[b,s,:]), :]
//
// Warp-autonomous minimal-tail scan: each warp owns a 125-float4 (2 KB)
// segment. Common path = 4x LDG.128 + raw-bit OR + one ballot, then exit
// (~30 cyc tail, no FFMA/shfl-reduce chain). The 1-in-512 warp that holds
// the 1.0 recovers the index with exact integer ops (ffs + select + shfl)
// and gathers the weight row itself.

#define NROWS    1024
#define VEC_V    8000         // float4 per row
#define WSEG     125          // float4 per warp segment (2 KB)
#define WPB      8            // warps per block
#define THREADS  (WPB * 32)
#define VEC_E    192          // float4 per output row

__global__ __launch_bounds__(THREADS, 8)
void onehot_embed_kernel(const float4* __restrict__ oh,
                         const float4* __restrict__ w,
                         float4* __restrict__ out)
{
    const int unit  = blockIdx.x;          // 8192 CTAs
    const int row   = unit >> 3;
    const int wblk  = unit & 7;
    const int warp  = threadIdx.x >> 5;
    const int lane  = threadIdx.x & 31;
    const int wseg  = wblk * WPB + warp;   // 0..63 within row

    const float4* __restrict__ r = oh + (size_t)row * VEC_V + wseg * WSEG;

    // ---- front-batched loads: 3 unconditional + 1 predicated (125 = 3*32+29)
    const int i3 = lane + 96;
    float4 v0 = __ldcs(&r[lane]);
    float4 v1 = __ldcs(&r[lane + 32]);
    float4 v2 = __ldcs(&r[lane + 64]);
    float4 v3 = make_float4(0.f, 0.f, 0.f, 0.f);
    if (i3 < WSEG) v3 = __ldcs(&r[i3]);

    // ---- detection only: raw-bit OR per load, then per-lane ----
    unsigned m0 = __float_as_uint(v0.x) | __float_as_uint(v0.y) | __float_as_uint(v0.z) | __float_as_uint(v0.w);
    unsigned m1 = __float_as_uint(v1.x) | __float_as_uint(v1.y) | __float_as_uint(v1.z) | __float_as_uint(v1.w);
    unsigned m2 = __float_as_uint(v2.x) | __float_as_uint(v2.y) | __float_as_uint(v2.z) | __float_as_uint(v2.w);
    unsigned m3 = __float_as_uint(v3.x) | __float_as_uint(v3.y) | __float_as_uint(v3.z) | __float_as_uint(v3.w);
    unsigned m  = m0 | m1 | m2 | m3;

    unsigned found = __ballot_sync(0xffffffffu, m != 0u);
    if (found == 0u) return;               // common path: exit, ~30 cyc tail

    // ---- rare path (1 warp in 512): exact integer index recovery ----
    const int src = __ffs(found) - 1;      // owning lane

    // which of the 4 loads holds it (valid only in owning lane)
    int k;  float4 vs;
    if      (m0) { k = 0; vs = v0; }
    else if (m1) { k = 1; vs = v1; }
    else if (m2) { k = 2; vs = v2; }
    else         { k = 3; vs = v3; }
    // which component
    int c = __float_as_uint(vs.x) ? 0 :
            __float_as_uint(vs.y) ? 1 :
            __float_as_uint(vs.z) ? 2 : 3;

    const int gbase = wseg * WSEG;         // float4 base within row
    int idx_local = 4 * (gbase + lane + k * 32) + c;
    int idx = __shfl_sync(0xffffffffu, idx_local, src);

    // ---- gather weight row -> out row (192 float4, 6 per lane) ----
    const float4* __restrict__ wr = w   + (size_t)idx * VEC_E;
    float4*       __restrict__ o  = out + (size_t)row * VEC_E;
    #pragma unroll
    for (int j = lane; j < VEC_E; j += 32)
        o[j] = __ldg(&wr[j]);
}

extern "C" void kernel_launch(void* const* d_in, const int* in_sizes, int n_in,
                              void* d_out, int out_size)
{
    // metadata order: input (one-hot), weight. Defensive swap by size.
    const float4* oh = (const float4*)d_in[0];
    const float4* w  = (const float4*)d_in[1];
    if (n_in >= 2 && in_sizes[0] < in_sizes[1]) {  // weight (24.6M) < one-hot (32.8M)
        oh = (const float4*)d_in[1];
        w  = (const float4*)d_in[0];
    }
    onehot_embed_kernel<<<NROWS * 8, THREADS>>>(oh, w, (float4*)d_out);
}